// round 4
// baseline (speedup 1.0000x reference)
#include <cuda_runtime.h>

// LSTM: B=512, T=1000, IN=39, H=64 (4H=256 gates), OUT=48.
// Persistent kernel: 128 CTAs (1/SM), 256 threads, thread = gate.
// R4: Phase A operand broadcast moved OFF the shared-memory crossbar
// (R1-R3 were bound by 32-lane broadcast delivery: ~256KB/step/SM ~= 3300
// crossbar cyc) onto per-SMSP shfl rotation: each lane loads a DISTINCT
// x/h pair, then 52 rotation steps broadcast pairs to all lanes in
// registers. Per-gate FP sum order identical to R1.

#define B_    512
#define T_    1000
#define IN_   39
#define H_    64
#define G_    256   // 4*H
#define OUT_  48
#define ROWS  4
#define CTAS  (B_/ROWS)   // 128
#define NTHR  256

typedef unsigned long long u64;

__device__ __forceinline__ u64 fma2(u64 a, u64 b, u64 c) {
    u64 d;
    asm("fma.rn.f32x2 %0, %1, %2, %3;" : "=l"(d) : "l"(a), "l"(b), "l"(c));
    return d;
}
__device__ __forceinline__ u64 pack2(float lo, float hi) {
    u64 d;
    asm("mov.b64 %0, {%1, %2};" : "=l"(d) : "f"(lo), "f"(hi));
    return d;
}
__device__ __forceinline__ void unpack2(u64 v, float &lo, float &hi) {
    asm("mov.b64 {%0, %1}, %2;" : "=f"(lo), "=f"(hi) : "l"(v));
}
__device__ __forceinline__ u64 shfl64(u64 v, int src) {
    unsigned lo = (unsigned)v, hi = (unsigned)(v >> 32);
    lo = __shfl_sync(0xffffffffu, lo, src);
    hi = __shfl_sync(0xffffffffu, hi, src);
    return ((u64)hi << 32) | lo;
}
__device__ __forceinline__ float sigm(float x) {
    return __fdividef(1.0f, 1.0f + __expf(-x));
}
__device__ __forceinline__ float tanh_(float x) {
    float e = __expf(2.0f * x);               // 0 .. inf
    return 1.0f - __fdividef(2.0f, e + 1.0f); // -1 .. 1, no inf/inf
}

__global__ void __launch_bounds__(NTHR, 1)
lstm_persist_kernel(const float* __restrict__ x,
                    const float* __restrict__ W_ih,
                    const float* __restrict__ W_hh,
                    const float* __restrict__ b_ih,
                    const float* __restrict__ b_hh,
                    const float* __restrict__ W_out,
                    const float* __restrict__ b_out,
                    float* __restrict__ out)
{
    __shared__ __align__(16) float hs[ROWS][H_];      // hidden state
    __shared__ __align__(16) float gbuf[ROWS][G_];    // gate preactivations
    __shared__ __align__(16) u64   woutS[H_/2][OUT_]; // W_out pairs, [k-pair][o]

    const int tid  = threadIdx.x;
    const int lane = tid & 31;
    const int row0 = blockIdx.x * ROWS;

    // ---- per-thread gate weights in registers: [W_ih row | W_hh row] as 52 pairs ----
    u64 wv[52];
    {
        const int g = tid;  // gate index 0..255
        #pragma unroll
        for (int k2 = 0; k2 < 20; k2++) {
            float lo = (2*k2     < IN_) ? W_ih[g*IN_ + 2*k2    ] : 0.0f;
            float hi = (2*k2 + 1 < IN_) ? W_ih[g*IN_ + 2*k2 + 1] : 0.0f;
            wv[k2] = pack2(lo, hi);
        }
        #pragma unroll
        for (int k2 = 0; k2 < 32; k2++) {
            wv[20 + k2] = pack2(W_hh[g*H_ + 2*k2], W_hh[g*H_ + 2*k2 + 1]);
        }
    }
    const u64 bias2 = pack2(b_ih[tid] + b_hh[tid], 0.0f);
    const u64 zero2 = pack2(0.0f, 0.0f);

    // ---- stage output head (W_out pairs, transposed) in SMEM ----
    for (int idx = tid; idx < (H_/2)*OUT_; idx += NTHR) {
        int k2 = idx / OUT_, o = idx % OUT_;
        woutS[k2][o] = pack2(W_out[o*H_ + 2*k2], W_out[o*H_ + 2*k2 + 1]);
    }

    // ---- zero h state ----
    hs[tid >> 6][tid & 63] = 0.0f;

    // ---- per-thread output-head constants ----
    int orow = 0, ocol = 0;
    u64 bo2 = zero2;
    if (tid < ROWS*OUT_) {
        orow = tid / OUT_;
        ocol = tid - orow*OUT_;
        bo2  = pack2(b_out[ocol], 0.0f);
    }

    const int ur = tid >> 6;   // row for cell-state update
    const int uu = tid & 63;   // hidden unit
    float creg = 0.0f;         // cell state register

    // ---- x lane-pair loading: lane i (i<20) sources pair (x[2i], x[2i+1]) ----
    // 39 is odd: lane 19's hi element is ZERO (wv[19].hi is also 0).
    const bool xl  = (lane < 20);
    const bool xl2 = (lane < 19);

    // current-step x pairs, one per row
    u64 xa0 = 0, xa1 = 0, xa2 = 0, xa3 = 0;
    if (xl) {
        #pragma unroll
        for (int r = 0; r < ROWS; r++) {
            const float* xb = x + ((size_t)(row0 + r) * T_) * IN_;
            float lo = xb[2*lane];
            float hi = xl2 ? xb[2*lane + 1] : 0.0f;
            u64 v = pack2(lo, hi);
            if (r == 0) xa0 = v; else if (r == 1) xa1 = v;
            else if (r == 2) xa2 = v; else xa3 = v;
        }
    }

    __syncthreads();

    for (int t = 0; t < T_; t++) {
        // ---- prefetch next step's x pairs (hidden behind Phase A) ----
        u64 xn0 = 0, xn1 = 0, xn2 = 0, xn3 = 0;
        const bool pf = xl && (t + 1 < T_);
        if (pf) {
            #pragma unroll
            for (int r = 0; r < ROWS; r++) {
                const float* xb = x + ((size_t)(row0 + r) * T_ + (t + 1)) * IN_;
                float lo = xb[2*lane];
                float hi = xl2 ? xb[2*lane + 1] : 0.0f;
                u64 v = pack2(lo, hi);
                if (r == 0) xn0 = v; else if (r == 1) xn1 = v;
                else if (r == 2) xn2 = v; else xn3 = v;
            }
        }

        // ---- Phase A: gate preactivations via shfl rotation, 4 rows interleaved ----
        {
            // lane-distinct h pair sources (lane l holds h[r][2l:2l+2])
            u64 h0 = ((const u64*)hs[0])[lane];
            u64 h1 = ((const u64*)hs[1])[lane];
            u64 h2 = ((const u64*)hs[2])[lane];
            u64 h3 = ((const u64*)hs[3])[lane];

            u64 a0 = bias2, a1 = bias2, a2 = bias2, a3 = bias2;

            #pragma unroll
            for (int j = 0; j < 20; j++) {
                u64 w = wv[j];
                a0 = fma2(w, shfl64(xa0, j), a0);
                a1 = fma2(w, shfl64(xa1, j), a1);
                a2 = fma2(w, shfl64(xa2, j), a2);
                a3 = fma2(w, shfl64(xa3, j), a3);
            }
            #pragma unroll
            for (int j = 0; j < 32; j++) {
                u64 w = wv[20 + j];
                a0 = fma2(w, shfl64(h0, j), a0);
                a1 = fma2(w, shfl64(h1, j), a1);
                a2 = fma2(w, shfl64(h2, j), a2);
                a3 = fma2(w, shfl64(h3, j), a3);
            }
            float lo, hi;
            unpack2(a0, lo, hi); gbuf[0][tid] = lo + hi;
            unpack2(a1, lo, hi); gbuf[1][tid] = lo + hi;
            unpack2(a2, lo, hi); gbuf[2][tid] = lo + hi;
            unpack2(a3, lo, hi); gbuf[3][tid] = lo + hi;
        }
        __syncthreads();

        // ---- Phase B: activations + cell/hidden update. thread -> (row, unit) ----
        {
            float gi = gbuf[ur][uu      ];
            float gf = gbuf[ur][uu +  64];
            float gg = gbuf[ur][uu + 128];
            float go = gbuf[ur][uu + 192];
            float iv = sigm(gi), fv = sigm(gf);
            float gv = tanh_(gg), ov = sigm(go);
            creg = fv * creg + iv * gv;
            hs[ur][uu] = ov * tanh_(creg);
        }
        __syncthreads();

        // ---- Phase C: output head y = sigmoid(h @ W_out^T + b_out) ----
        if (tid < ROWS*OUT_) {
            u64 acc0 = bo2, acc1 = zero2;
            const ulonglong2* hp = (const ulonglong2*)hs[orow];
            #pragma unroll
            for (int k = 0; k < 16; k += 2) {
                ulonglong2 qa = hp[k], qb = hp[k + 1];
                acc0 = fma2(woutS[2*k    ][ocol], qa.x, acc0);
                acc1 = fma2(woutS[2*k + 1][ocol], qa.y, acc1);
                acc0 = fma2(woutS[2*k + 2][ocol], qb.x, acc0);
                acc1 = fma2(woutS[2*k + 3][ocol], qb.y, acc1);
            }
            float l0, h0v, l1, h1v;
            unpack2(acc0, l0, h0v);
            unpack2(acc1, l1, h1v);
            out[((size_t)(row0 + orow) * T_ + t) * OUT_ + ocol] =
                sigm((l0 + h0v) + (l1 + h1v));
        }

        // rotate prefetched x into place
        xa0 = xn0; xa1 = xn1; xa2 = xn2; xa3 = xn3;

        // No extra sync: Phase C reads hs (finalized before the barrier above);
        // next Phase A reads hs via lane loads and writes gbuf, whose Phase-B
        // readers finished before that same barrier. hs is next written in
        // Phase B, after the next Phase-A barrier.
    }
}

extern "C" void kernel_launch(void* const* d_in, const int* in_sizes, int n_in,
                              void* d_out, int out_size)
{
    (void)in_sizes; (void)n_in; (void)out_size;
    const float* x     = (const float*)d_in[0];
    const float* W_ih  = (const float*)d_in[1];
    const float* W_hh  = (const float*)d_in[2];
    const float* b_ih  = (const float*)d_in[3];
    const float* b_hh  = (const float*)d_in[4];
    const float* W_out = (const float*)d_in[5];
    const float* b_out = (const float*)d_in[6];
    float* out = (float*)d_out;

    lstm_persist_kernel<<<CTAS, NTHR>>>(x, W_ih, W_hh, b_ih, b_hh, W_out, b_out, out);
}

// round 5
// speedup vs baseline: 1.4692x; 1.4692x over previous
#include <cuda_runtime.h>

// LSTM: B=512, T=1000, IN=39, H=64 (4H=256 gates), OUT=48.
// Persistent kernel: 128 CTAs (1/SM), 512 threads.
// R5: thread = (gate, k-half). K=52 weight pairs split 26/26 across two
// thread groups -> 52 weight regs/thread (no spill, unlike R3's 128-reg cap)
// and 4 warps/SMSP to overlap the FMA stream (~832 cyc/SM/step floor) with
// the broadcast-LDS stream (~850 wavefronts/SM/step). R4 proved MIO op
// count is the wall and SHFL is 4x worse than broadcast LDS.128.

#define B_    512
#define T_    1000
#define IN_   39
#define H_    64
#define G_    256   // 4*H
#define OUT_  48
#define ROWS  4
#define CTAS  (B_/ROWS)   // 128
#define NTHR  512

typedef unsigned long long u64;

__device__ __forceinline__ u64 fma2(u64 a, u64 b, u64 c) {
    u64 d;
    asm("fma.rn.f32x2 %0, %1, %2, %3;" : "=l"(d) : "l"(a), "l"(b), "l"(c));
    return d;
}
__device__ __forceinline__ u64 pack2(float lo, float hi) {
    u64 d;
    asm("mov.b64 %0, {%1, %2};" : "=l"(d) : "f"(lo), "f"(hi));
    return d;
}
__device__ __forceinline__ void unpack2(u64 v, float &lo, float &hi) {
    asm("mov.b64 {%0, %1}, %2;" : "=f"(lo), "=f"(hi) : "l"(v));
}
__device__ __forceinline__ float sigm(float x) {
    return __fdividef(1.0f, 1.0f + __expf(-x));
}
__device__ __forceinline__ float tanh_(float x) {
    float e = __expf(2.0f * x);               // 0 .. inf
    return 1.0f - __fdividef(2.0f, e + 1.0f); // -1 .. 1, no inf/inf
}

__global__ void __launch_bounds__(NTHR, 1)
lstm_persist_kernel(const float* __restrict__ x,
                    const float* __restrict__ W_ih,
                    const float* __restrict__ W_hh,
                    const float* __restrict__ b_ih,
                    const float* __restrict__ b_hh,
                    const float* __restrict__ W_out,
                    const float* __restrict__ b_out,
                    float* __restrict__ out)
{
    __shared__ __align__(16) float xs[2][ROWS][40];   // x slice, double-buffered, 39->40 pad
    __shared__ __align__(16) float hs[ROWS][H_];      // hidden state
    __shared__ __align__(16) float gA[ROWS][G_];      // gate partials, k-half 0
    __shared__ __align__(16) float gB[ROWS][G_];      // gate partials, k-half 1
    __shared__ __align__(16) u64   woutS[H_/2][OUT_]; // W_out pairs, [k-pair][o]

    const int tid  = threadIdx.x;
    const int g    = tid & 255;   // gate 0..255
    const int kh   = tid >> 8;    // k-half: 0 -> x[0..39)+h[0..12), 1 -> h[12..64)
    const int row0 = blockIdx.x * ROWS;

    // ---- per-thread weights: 26 f32x2 pairs ----
    u64 wv[26];
    if (kh == 0) {
        #pragma unroll
        for (int k2 = 0; k2 < 20; k2++) {
            float lo = (2*k2     < IN_) ? W_ih[g*IN_ + 2*k2    ] : 0.0f;
            float hi = (2*k2 + 1 < IN_) ? W_ih[g*IN_ + 2*k2 + 1] : 0.0f;
            wv[k2] = pack2(lo, hi);
        }
        #pragma unroll
        for (int k2 = 0; k2 < 6; k2++)   // h pairs 0..5 (cols 0..11)
            wv[20 + k2] = pack2(W_hh[g*H_ + 2*k2], W_hh[g*H_ + 2*k2 + 1]);
    } else {
        #pragma unroll
        for (int k2 = 0; k2 < 26; k2++)  // h pairs 6..31 (cols 12..63)
            wv[k2] = pack2(W_hh[g*H_ + 12 + 2*k2], W_hh[g*H_ + 13 + 2*k2]);
    }
    const u64 zero2 = pack2(0.0f, 0.0f);
    const u64 bias2 = (kh == 0) ? pack2(b_ih[g] + b_hh[g], 0.0f) : zero2;

    // ---- stage output head (W_out pairs, transposed) in SMEM ----
    for (int idx = tid; idx < (H_/2)*OUT_; idx += NTHR) {
        int k2 = idx / OUT_, o = idx % OUT_;
        woutS[k2][o] = pack2(W_out[o*H_ + 2*k2], W_out[o*H_ + 2*k2 + 1]);
    }

    // ---- zero h state and x buffers (incl. pad elements) ----
    if (tid < ROWS*H_) hs[tid >> 6][tid & 63] = 0.0f;
    for (int idx = tid; idx < 2*ROWS*40; idx += NTHR)
        ((float*)xs)[idx] = 0.0f;
    __syncthreads();

    // ---- t=0 x slice ----
    if (tid < ROWS*IN_) {
        int r = tid / IN_, i = tid % IN_;
        xs[0][r][i] = x[((size_t)(row0 + r) * T_) * IN_ + i];
    }

    // ---- per-thread output-head constants ----
    int orow = 0, ocol = 0;
    u64 bo2 = zero2;
    if (tid < ROWS*OUT_) {
        orow = tid / OUT_;
        ocol = tid - orow*OUT_;
        bo2  = pack2(b_out[ocol], 0.0f);
    }

    const int ur = (tid >> 6) & 3;   // row for cell update (tid<256)
    const int uu = tid & 63;         // hidden unit
    float creg = 0.0f;               // cell state register (tid<256)

    // prefetch mapping (valid when tid < ROWS*IN_ = 156, all in kh==0 warps)
    const int pr = (tid < ROWS*IN_) ? (tid / IN_) : 0;
    const int pi = (tid < ROWS*IN_) ? (tid % IN_) : 0;

    __syncthreads();

    for (int t = 0; t < T_; t++) {
        const int p = t & 1;

        // prefetch next timestep's x into a register (hidden behind Phase A)
        float xv = 0.0f;
        const bool pf = (tid < ROWS*IN_) && (t + 1 < T_);
        if (pf) xv = x[((size_t)(row0 + pr) * T_ + (t + 1)) * IN_ + pi];

        // ---- Phase A: partial gate preactivations, 4 rows interleaved ----
        {
            u64 a0 = bias2, a1 = bias2, a2 = bias2, a3 = bias2;

            if (kh == 0) {
                const ulonglong2* xp0 = (const ulonglong2*)xs[p][0];
                const ulonglong2* xp1 = (const ulonglong2*)xs[p][1];
                const ulonglong2* xp2 = (const ulonglong2*)xs[p][2];
                const ulonglong2* xp3 = (const ulonglong2*)xs[p][3];
                #pragma unroll
                for (int k = 0; k < 10; k++) {
                    ulonglong2 q0 = xp0[k], q1 = xp1[k], q2 = xp2[k], q3 = xp3[k];
                    u64 wa = wv[2*k], wb = wv[2*k + 1];
                    a0 = fma2(wa, q0.x, a0); a1 = fma2(wa, q1.x, a1);
                    a2 = fma2(wa, q2.x, a2); a3 = fma2(wa, q3.x, a3);
                    a0 = fma2(wb, q0.y, a0); a1 = fma2(wb, q1.y, a1);
                    a2 = fma2(wb, q2.y, a2); a3 = fma2(wb, q3.y, a3);
                }
                const ulonglong2* hp0 = (const ulonglong2*)hs[0];
                const ulonglong2* hp1 = (const ulonglong2*)hs[1];
                const ulonglong2* hp2 = (const ulonglong2*)hs[2];
                const ulonglong2* hp3 = (const ulonglong2*)hs[3];
                #pragma unroll
                for (int k = 0; k < 3; k++) {
                    ulonglong2 q0 = hp0[k], q1 = hp1[k], q2 = hp2[k], q3 = hp3[k];
                    u64 wa = wv[20 + 2*k], wb = wv[21 + 2*k];
                    a0 = fma2(wa, q0.x, a0); a1 = fma2(wa, q1.x, a1);
                    a2 = fma2(wa, q2.x, a2); a3 = fma2(wa, q3.x, a3);
                    a0 = fma2(wb, q0.y, a0); a1 = fma2(wb, q1.y, a1);
                    a2 = fma2(wb, q2.y, a2); a3 = fma2(wb, q3.y, a3);
                }
                float lo, hi;
                unpack2(a0, lo, hi); gA[0][g] = lo + hi;
                unpack2(a1, lo, hi); gA[1][g] = lo + hi;
                unpack2(a2, lo, hi); gA[2][g] = lo + hi;
                unpack2(a3, lo, hi); gA[3][g] = lo + hi;
            } else {
                // h pairs 6..31 = floats 12..63 (16B-aligned offset)
                const ulonglong2* hp0 = (const ulonglong2*)(hs[0] + 12);
                const ulonglong2* hp1 = (const ulonglong2*)(hs[1] + 12);
                const ulonglong2* hp2 = (const ulonglong2*)(hs[2] + 12);
                const ulonglong2* hp3 = (const ulonglong2*)(hs[3] + 12);
                #pragma unroll
                for (int k = 0; k < 13; k++) {
                    ulonglong2 q0 = hp0[k], q1 = hp1[k], q2 = hp2[k], q3 = hp3[k];
                    u64 wa = wv[2*k], wb = wv[2*k + 1];
                    a0 = fma2(wa, q0.x, a0); a1 = fma2(wa, q1.x, a1);
                    a2 = fma2(wa, q2.x, a2); a3 = fma2(wa, q3.x, a3);
                    a0 = fma2(wb, q0.y, a0); a1 = fma2(wb, q1.y, a1);
                    a2 = fma2(wb, q2.y, a2); a3 = fma2(wb, q3.y, a3);
                }
                float lo, hi;
                unpack2(a0, lo, hi); gB[0][g] = lo + hi;
                unpack2(a1, lo, hi); gB[1][g] = lo + hi;
                unpack2(a2, lo, hi); gB[2][g] = lo + hi;
                unpack2(a3, lo, hi); gB[3][g] = lo + hi;
            }
        }
        __syncthreads();

        // ---- Phase B: combine partials + activations + state update (tid<256) ----
        if (tid < ROWS*H_) {
            float gi = gA[ur][uu      ] + gB[ur][uu      ];
            float gf = gA[ur][uu +  64] + gB[ur][uu +  64];
            float gg = gA[ur][uu + 128] + gB[ur][uu + 128];
            float go = gA[ur][uu + 192] + gB[ur][uu + 192];
            float iv = sigm(gi), fv = sigm(gf);
            float gv = tanh_(gg), ov = sigm(go);
            creg = fv * creg + iv * gv;
            hs[ur][uu] = ov * tanh_(creg);
        }
        if (pf) xs[p ^ 1][pr][pi] = xv;  // publish prefetched x for next step
        __syncthreads();

        // ---- Phase C: output head y = sigmoid(h @ W_out^T + b_out) ----
        if (tid < ROWS*OUT_) {
            u64 acc0 = bo2, acc1 = zero2;
            const ulonglong2* hp = (const ulonglong2*)hs[orow];
            #pragma unroll
            for (int k = 0; k < 16; k += 2) {
                ulonglong2 qa = hp[k], qb = hp[k + 1];
                acc0 = fma2(woutS[2*k    ][ocol], qa.x, acc0);
                acc1 = fma2(woutS[2*k + 1][ocol], qa.y, acc1);
                acc0 = fma2(woutS[2*k + 2][ocol], qb.x, acc0);
                acc1 = fma2(woutS[2*k + 3][ocol], qb.y, acc1);
            }
            float l0, h0v, l1, h1v;
            unpack2(acc0, l0, h0v);
            unpack2(acc1, l1, h1v);
            out[((size_t)(row0 + orow) * T_ + t) * OUT_ + ocol] =
                sigm((l0 + h0v) + (l1 + h1v));
        }
        // No extra sync: Phase C reads hs (finalized before the barrier above);
        // next Phase A reads hs/xs and writes gA/gB, whose Phase-B readers
        // finished before that same barrier. hs is next written in Phase B,
        // after the next Phase-A barrier.
    }
}

extern "C" void kernel_launch(void* const* d_in, const int* in_sizes, int n_in,
                              void* d_out, int out_size)
{
    (void)in_sizes; (void)n_in; (void)out_size;
    const float* x     = (const float*)d_in[0];
    const float* W_ih  = (const float*)d_in[1];
    const float* W_hh  = (const float*)d_in[2];
    const float* b_ih  = (const float*)d_in[3];
    const float* b_hh  = (const float*)d_in[4];
    const float* W_out = (const float*)d_in[5];
    const float* b_out = (const float*)d_in[6];
    float* out = (float*)d_out;

    lstm_persist_kernel<<<CTAS, NTHR>>>(x, W_ih, W_hh, b_ih, b_hh, W_out, b_out, out);
}